// round 5
// baseline (speedup 1.0000x reference)
#include <cuda_runtime.h>
#include <cuda_bf16.h>
#include <cstdint>

#define NSP 100000
#define NRX 200000
#define NED 1000000
#define DM  128
#define BGR 50
#define NS_PER 2000
#define NR_PER 4000

// Scratch buffers (static device globals)
__device__ float g_hsA[NSP * DM];
__device__ float g_hsB[NSP * DM];
__device__ float g_hrA[NRX * DM];
__device__ float g_hrB[NRX * DM];
__device__ float g_y[NSP * DM];    // Y = relu?(h_s) @ Wr2
__device__ float g_z[NRX * DM];    // Z = relu(h_r)  @ Ws2
// Pre-transposed, hi/lo-split weights: [which of 4][hi=0/lo=1][n=128][k=256] bf16
__device__ __nv_bfloat16 g_wt[4][2][128 * 256];

// ---------------------------------------------------------------------------
__device__ __forceinline__ uint32_t smem_u32(const void* p) {
    uint32_t a;
    asm("{ .reg .u64 t; cvta.to.shared.u64 t, %1; cvt.u32.u64 %0, t; }" : "=r"(a) : "l"(p));
    return a;
}
__device__ __forceinline__ void ldsm4(uint32_t r[4], uint32_t addr) {
    asm volatile("ldmatrix.sync.aligned.m8n8.x4.shared.b16 {%0,%1,%2,%3}, [%4];"
                 : "=r"(r[0]), "=r"(r[1]), "=r"(r[2]), "=r"(r[3]) : "r"(addr));
}
__device__ __forceinline__ void mma16816(float c[4], const uint32_t a[4],
                                         uint32_t b0, uint32_t b1) {
    asm volatile(
        "mma.sync.aligned.m16n8k16.row.col.f32.bf16.bf16.f32 "
        "{%0,%1,%2,%3}, {%4,%5,%6,%7}, {%8,%9}, {%0,%1,%2,%3};"
        : "+f"(c[0]), "+f"(c[1]), "+f"(c[2]), "+f"(c[3])
        : "r"(a[0]), "r"(a[1]), "r"(a[2]), "r"(a[3]), "r"(b0), "r"(b1));
}

// ---------------------------------------------------------------------------
// Init kernels
__global__ void k_init_hs(const int* __restrict__ sidx, const int* __restrict__ ext,
                          const float* __restrict__ st, const float* __restrict__ et,
                          float* __restrict__ hs) {
    int t = blockIdx.x * blockDim.x + threadIdx.x;
    int row = t >> 5, c = t & 31;
    if (row >= NSP) return;
    int si = sidx[row], ei = ext[row];
    float4 a = ((const float4*)st)[si * 32 + c];
    float4 b = ((const float4*)et)[ei * 32 + c];
    float4 o;
    o.x = a.x + b.x; o.y = a.y + b.y; o.z = a.z + b.z; o.w = a.w + b.w;
    ((float4*)hs)[row * 32 + c] = o;
}

__global__ void k_init_hr(const int* __restrict__ tids, const float* __restrict__ params,
                          const float* __restrict__ tt, const float* __restrict__ Wp,
                          const float* __restrict__ bp, float* __restrict__ hr) {
    int t = blockIdx.x * blockDim.x + threadIdx.x;
    int row = t >> 5, c = t & 31;
    if (row >= NRX) return;
    int ti = tids[row];
    float4 acc = ((const float4*)tt)[ti * 32 + c];
    float4 bb  = ((const float4*)bp)[c];
    acc.x += bb.x; acc.y += bb.y; acc.z += bb.z; acc.w += bb.w;
#pragma unroll
    for (int k = 0; k < 8; k++) {
        float p = params[row * 8 + k];
        float4 w = ((const float4*)Wp)[k * 32 + c];
        acc.x += p * w.x; acc.y += p * w.y; acc.z += p * w.z; acc.w += p * w.w;
    }
    ((float4*)hr)[row * 32 + c] = acc;
}

// ---------------------------------------------------------------------------
// Segment sum, 4 edges per warp for MLP: dst[ed[e]] += src[es[e]]
__global__ void k_seg4(const float* __restrict__ src, float* __restrict__ dst,
                       const int* __restrict__ es, const int* __restrict__ ed) {
    int t = blockIdx.x * blockDim.x + threadIdx.x;
    int w = t >> 5, lane = t & 31;
    int e0 = w * 4;
    if (e0 >= NED) return;
    int4 s4 = *(const int4*)(es + e0);
    int4 d4 = *(const int4*)(ed + e0);
    const float4* src4 = (const float4*)src;
    float4 v0 = src4[(size_t)s4.x * 32 + lane];
    float4 v1 = src4[(size_t)s4.y * 32 + lane];
    float4 v2 = src4[(size_t)s4.z * 32 + lane];
    float4 v3 = src4[(size_t)s4.w * 32 + lane];
    float* p0 = dst + (size_t)d4.x * DM + lane * 4;
    float* p1 = dst + (size_t)d4.y * DM + lane * 4;
    float* p2 = dst + (size_t)d4.z * DM + lane * 4;
    float* p3 = dst + (size_t)d4.w * DM + lane * 4;
    asm volatile("red.global.add.v4.f32 [%0], {%1, %2, %3, %4};"
                 :: "l"(p0), "f"(v0.x), "f"(v0.y), "f"(v0.z), "f"(v0.w) : "memory");
    asm volatile("red.global.add.v4.f32 [%0], {%1, %2, %3, %4};"
                 :: "l"(p1), "f"(v1.x), "f"(v1.y), "f"(v1.z), "f"(v1.w) : "memory");
    asm volatile("red.global.add.v4.f32 [%0], {%1, %2, %3, %4};"
                 :: "l"(p2), "f"(v2.x), "f"(v2.y), "f"(v2.z), "f"(v2.w) : "memory");
    asm volatile("red.global.add.v4.f32 [%0], {%1, %2, %3, %4};"
                 :: "l"(p3), "f"(v3.x), "f"(v3.y), "f"(v3.z), "f"(v3.w) : "memory");
}

// ---------------------------------------------------------------------------
// W prep: transpose + hi/lo bf16 split.  g_wt[l][h][n*256+k]
// l order: 0=Wr[0], 1=Ws[0], 2=Wr[1], 3=Ws[1]
__global__ void k_prep_w(const float* __restrict__ Wr, const float* __restrict__ Ws) {
    int idx = blockIdx.x * blockDim.x + threadIdx.x;
    if (idx >= 4 * 256 * 128) return;
    int l = idx >> 15;
    int rem = idx & 32767;
    int k = rem >> 7, n = rem & 127;
    const float* src = (l & 1) ? (Ws + (size_t)(l >> 1) * 2 * DM * DM)
                               : (Wr + (size_t)(l >> 1) * 2 * DM * DM);
    float w = src[k * DM + n];
    __nv_bfloat16 hi = __float2bfloat16(w);
    float lo = w - __bfloat162float(hi);
    g_wt[l][0][n * 256 + k] = hi;
    g_wt[l][1][n * 256 + k] = __float2bfloat16(lo);
}

// ---------------------------------------------------------------------------
// Tensor-core GEMM (K=128):  D[row] = relu?(X[row]) @ W[koff:koff+128] (+ bias)
// 512 threads (16 warps), CTA tile 128x128, warp tile 16x64 (8m x 2n warps).
// bf16 hi/lo split: acc = Xh@Wh + Xl@Wh + Xh@Wl  (fp32 accumulate).
#define PITCH 72
#define PB    (PITCH * 2)
#define TILEB (128 * PB)

template<bool RELU_IN, bool HAS_BIAS>
__global__ void __launch_bounds__(512, 1) k_gemm_mma(
    float* __restrict__ D, const float* __restrict__ X,
    const __nv_bfloat16* __restrict__ Wth, const __nv_bfloat16* __restrict__ Wtl,
    const float* __restrict__ bias, int n, int koff)
{
    extern __shared__ char sm[];
    char* pXH = sm;
    char* pXL = sm + TILEB;
    char* pWH = sm + 2 * TILEB;
    char* pWL = sm + 3 * TILEB;
    uint32_t aXH = smem_u32(pXH), aXL = smem_u32(pXL);
    uint32_t aWH = smem_u32(pWH), aWL = smem_u32(pWL);

    int tid = threadIdx.x;
    int lane = tid & 31, wid = tid >> 5;
    int wm = (wid & 7) * 16;          // 8 m-groups of 16 rows
    int wn = (wid >> 3) * 64;         // 2 n-groups of 64 cols
    int rowBase = blockIdx.x * 128;

    // ldmatrix lane-address offsets (bytes within a tile)
    uint32_t aOff = (uint32_t)(wm + (lane & 15)) * PB + ((lane >> 4) * 8) * 2;
    uint32_t bOff = (uint32_t)(wn + (lane & 7) + ((lane >> 4) & 1) * 8) * PB
                  + (((lane >> 3) & 1) * 8) * 2;

    float acc[8][4];
#pragma unroll
    for (int nt = 0; nt < 8; nt++)
#pragma unroll
        for (int j = 0; j < 4; j++) acc[nt][j] = 0.f;

#pragma unroll
    for (int ch = 0; ch < 2; ch++) {
        int kq = ch * 16;
        // ---- X chunk: 128 rows x 64 k fp32 -> (relu) -> bf16 hi/lo ----
#pragma unroll
        for (int i = 0; i < 4; i++) {
            int f = i * 512 + tid;
            int r = f >> 4, c = f & 15;
            int gr = rowBase + r;
            float4 v = make_float4(0.f, 0.f, 0.f, 0.f);
            if (gr < n) v = ((const float4*)X)[gr * 32 + kq + c];
            if (RELU_IN) {
                v.x = fmaxf(v.x, 0.f); v.y = fmaxf(v.y, 0.f);
                v.z = fmaxf(v.z, 0.f); v.w = fmaxf(v.w, 0.f);
            }
            __nv_bfloat16 h0 = __float2bfloat16(v.x);
            __nv_bfloat16 h1 = __float2bfloat16(v.y);
            __nv_bfloat16 h2 = __float2bfloat16(v.z);
            __nv_bfloat16 h3 = __float2bfloat16(v.w);
            __nv_bfloat162 hh[2], ll[2];
            hh[0].x = h0; hh[0].y = h1; hh[1].x = h2; hh[1].y = h3;
            ll[0].x = __float2bfloat16(v.x - __bfloat162float(h0));
            ll[0].y = __float2bfloat16(v.y - __bfloat162float(h1));
            ll[1].x = __float2bfloat16(v.z - __bfloat162float(h2));
            ll[1].y = __float2bfloat16(v.w - __bfloat162float(h3));
            uint32_t off = (uint32_t)r * PB + c * 8;
            *(uint2*)(pXH + off) = *(uint2*)hh;
            *(uint2*)(pXL + off) = *(uint2*)ll;
        }
        // ---- W chunk: 128 n x 64 k bf16 (pre-transposed/split) ----
#pragma unroll
        for (int i = 0; i < 2; i++) {
            int f = i * 512 + tid;
            int r = f >> 3, c = f & 7;
            size_t goff = (size_t)r * 256 + koff + ch * 64 + c * 8;
            uint32_t off = (uint32_t)r * PB + c * 16;
            *(uint4*)(pWH + off) = *(const uint4*)(Wth + goff);
            *(uint4*)(pWL + off) = *(const uint4*)(Wtl + goff);
        }
        __syncthreads();

        // ---- 3 products x 4 k16-steps ----
#pragma unroll
        for (int p = 0; p < 3; p++) {
            uint32_t aBase = (p == 1) ? aXL : aXH;
            uint32_t bBase = (p == 2) ? aWL : aWH;
#pragma unroll
            for (int ks = 0; ks < 4; ks++) {
                uint32_t aF[4];
                ldsm4(aF, aBase + aOff + ks * 32);
                uint32_t bF[4][4];
#pragma unroll
                for (int q = 0; q < 4; q++)
                    ldsm4(bF[q], bBase + bOff + ks * 32 + q * 16 * PB);
#pragma unroll
                for (int q = 0; q < 4; q++) {
                    mma16816(acc[q * 2 + 0], aF, bF[q][0], bF[q][1]);
                    mma16816(acc[q * 2 + 1], aF, bF[q][2], bF[q][3]);
                }
            }
        }
        __syncthreads();
    }

    // ---- epilogue: (+bias), NO relu (deferred to consumers) ----
    int r0 = (lane >> 2);
    int c0 = (lane & 3) * 2;
    int rowA = rowBase + wm + r0;
    int rowB = rowA + 8;
#pragma unroll
    for (int nt = 0; nt < 8; nt++) {
        int col = wn + nt * 8 + c0;
        float2 b2 = make_float2(0.f, 0.f);
        if (HAS_BIAS) b2 = *(const float2*)&bias[col];
        if (rowA < n) {
            float2 o;
            o.x = acc[nt][0] + b2.x;
            o.y = acc[nt][1] + b2.y;
            *(float2*)&D[(size_t)rowA * DM + col] = o;
        }
        if (rowB < n) {
            float2 o;
            o.x = acc[nt][2] + b2.x;
            o.y = acc[nt][3] + b2.y;
            *(float2*)&D[(size_t)rowB * DM + col] = o;
        }
    }
}

// ---------------------------------------------------------------------------
// Pool with deferred relu on inputs
__global__ void k_pool(const float* __restrict__ hs, const float* __restrict__ hr,
                       float* __restrict__ out) {
    int kind = blockIdx.z;
    int b = blockIdx.y;
    int col = blockIdx.x * 32 + (threadIdx.x & 31);
    int g = threadIdx.x >> 5;
    const float* h = kind ? hr : hs;
    int np = kind ? NR_PER : NS_PER;
    float inv = kind ? (1.f / NR_PER) : (1.f / NS_PER);
    size_t base = (size_t)b * np * DM;
    float s = 0.f;
    for (int i = g; i < np; i += 8)
        s += fmaxf(h[base + (size_t)i * DM + col], 0.f);
    __shared__ float red[8][32];
    red[g][threadIdx.x & 31] = s;
    __syncthreads();
    if (g == 0) {
        float tot = 0.f;
#pragma unroll
        for (int j = 0; j < 8; j++) tot += red[j][threadIdx.x & 31];
        out[b * 256 + kind * 128 + col] = tot * inv;
    }
}

// ---------------------------------------------------------------------------
extern "C" void kernel_launch(void* const* d_in, const int* in_sizes, int n_in,
                              void* d_out, int out_size) {
    const int*   species_indices = (const int*)  d_in[0];
    const int*   is_external     = (const int*)  d_in[1];
    const int*   prop_type_ids   = (const int*)  d_in[2];
    const float* prop_params     = (const float*)d_in[3];
    const int*   edge_species    = (const int*)  d_in[4];
    const int*   edge_reaction   = (const int*)  d_in[5];
    const float* species_table   = (const float*)d_in[8];
    const float* external_table  = (const float*)d_in[9];
    const float* type_table      = (const float*)d_in[10];
    const float* W_param         = (const float*)d_in[11];
    const float* b_param         = (const float*)d_in[12];
    const float* Wr              = (const float*)d_in[13];
    const float* br              = (const float*)d_in[14];
    const float* Ws              = (const float*)d_in[15];
    const float* bs              = (const float*)d_in[16];
    float* out = (float*)d_out;

    float *hsA, *hsB, *hrA, *hrB, *y, *z;
    __nv_bfloat16* wt;
    cudaGetSymbolAddress((void**)&hsA, g_hsA);
    cudaGetSymbolAddress((void**)&hsB, g_hsB);
    cudaGetSymbolAddress((void**)&hrA, g_hrA);
    cudaGetSymbolAddress((void**)&hrB, g_hrB);
    cudaGetSymbolAddress((void**)&y, g_y);
    cudaGetSymbolAddress((void**)&z, g_z);
    cudaGetSymbolAddress((void**)&wt, g_wt);

    const int GEMM_SMEM = 4 * TILEB;
    cudaFuncSetAttribute(k_gemm_mma<false, false>, cudaFuncAttributeMaxDynamicSharedMemorySize, GEMM_SMEM);
    cudaFuncSetAttribute(k_gemm_mma<false, true>,  cudaFuncAttributeMaxDynamicSharedMemorySize, GEMM_SMEM);
    cudaFuncSetAttribute(k_gemm_mma<true, false>,  cudaFuncAttributeMaxDynamicSharedMemorySize, GEMM_SMEM);
    cudaFuncSetAttribute(k_gemm_mma<true, true>,   cudaFuncAttributeMaxDynamicSharedMemorySize, GEMM_SMEM);

    k_init_hs<<<(NSP * 32 + 255) / 256, 256>>>(species_indices, is_external,
                                               species_table, external_table, hsA);
    k_init_hr<<<(NRX * 32 + 255) / 256, 256>>>(prop_type_ids, prop_params,
                                               type_table, W_param, b_param, hrA);
    k_prep_w<<<512, 256>>>(Wr, Ws);

    const int segBlocks = (NED / 4 * 32 + 255) / 256;   // 31250
    const int gS = (NSP + 127) / 128, gR = (NRX + 127) / 128;
    const size_t WSZ = (size_t)2 * 128 * 256;

    // ---- layer 0 (inputs have no relu) ----
    {
        const __nv_bfloat16* WrH = wt + 0 * WSZ;  const __nv_bfloat16* WrL = WrH + 128 * 256;
        const __nv_bfloat16* WsH = wt + 1 * WSZ;  const __nv_bfloat16* WsL = WsH + 128 * 256;
        k_gemm_mma<false, false><<<gS, 512, GEMM_SMEM>>>(y,   hsA, WrH, WrL, nullptr, NSP, 128);
        k_gemm_mma<false, true ><<<gR, 512, GEMM_SMEM>>>(hrB, hrA, WrH, WrL, br,      NRX, 0);
        k_seg4<<<segBlocks, 256>>>(y, hrB, edge_species, edge_reaction);
        k_gemm_mma<true,  false><<<gR, 512, GEMM_SMEM>>>(z,   hrB, WsH, WsL, nullptr, NRX, 128);
        k_gemm_mma<false, true ><<<gS, 512, GEMM_SMEM>>>(hsB, hsA, WsH, WsL, bs,      NSP, 0);
        k_seg4<<<segBlocks, 256>>>(z, hsB, edge_reaction, edge_species);
    }
    // ---- layer 1 (inputs need relu) ----
    {
        const __nv_bfloat16* WrH = wt + 2 * WSZ;  const __nv_bfloat16* WrL = WrH + 128 * 256;
        const __nv_bfloat16* WsH = wt + 3 * WSZ;  const __nv_bfloat16* WsL = WsH + 128 * 256;
        const float* br1 = br + DM;
        const float* bs1 = bs + DM;
        k_gemm_mma<true, false><<<gS, 512, GEMM_SMEM>>>(y,   hsB, WrH, WrL, nullptr, NSP, 128);
        k_gemm_mma<true, true ><<<gR, 512, GEMM_SMEM>>>(hrA, hrB, WrH, WrL, br1,     NRX, 0);
        k_seg4<<<segBlocks, 256>>>(y, hrA, edge_species, edge_reaction);
        k_gemm_mma<true, false><<<gR, 512, GEMM_SMEM>>>(z,   hrA, WsH, WsL, nullptr, NRX, 128);
        k_gemm_mma<true, true ><<<gS, 512, GEMM_SMEM>>>(hsA, hsB, WsH, WsL, bs1,     NSP, 0);
        k_seg4<<<segBlocks, 256>>>(z, hsA, edge_reaction, edge_species);
    }

    k_pool<<<dim3(4, BGR, 2), 256>>>(hsA, hrA, out);
}

// round 6
// speedup vs baseline: 1.3098x; 1.3098x over previous
#include <cuda_runtime.h>
#include <cuda_fp16.h>
#include <cstdint>

#define NSP 100000
#define NRX 200000
#define NED 1000000
#define DM  128
#define BGR 50
#define NS_PER 2000
#define NR_PER 4000

// Scratch buffers (static device globals)
__device__ float g_hsA[NSP * DM];
__device__ float g_hsB[NSP * DM];
__device__ float g_hrA[NRX * DM];
__device__ float g_hrB[NRX * DM];
__device__ float g_y[NSP * DM];    // Y = relu?(h_s) @ Wr2
__device__ float g_z[NRX * DM];    // Z = relu(h_r)  @ Ws2
// Pre-transposed fp16 weights: [which of 4][n=128][k=256]
__device__ __half g_wt[4][128 * 256];

// ---------------------------------------------------------------------------
__device__ __forceinline__ uint32_t smem_u32(const void* p) {
    uint32_t a;
    asm("{ .reg .u64 t; cvta.to.shared.u64 t, %1; cvt.u32.u64 %0, t; }" : "=r"(a) : "l"(p));
    return a;
}
__device__ __forceinline__ void ldsm4(uint32_t r[4], uint32_t addr) {
    asm volatile("ldmatrix.sync.aligned.m8n8.x4.shared.b16 {%0,%1,%2,%3}, [%4];"
                 : "=r"(r[0]), "=r"(r[1]), "=r"(r[2]), "=r"(r[3]) : "r"(addr));
}
__device__ __forceinline__ void mma16816(float c[4], const uint32_t a[4],
                                         uint32_t b0, uint32_t b1) {
    asm volatile(
        "mma.sync.aligned.m16n8k16.row.col.f32.f16.f16.f32 "
        "{%0,%1,%2,%3}, {%4,%5,%6,%7}, {%8,%9}, {%0,%1,%2,%3};"
        : "+f"(c[0]), "+f"(c[1]), "+f"(c[2]), "+f"(c[3])
        : "r"(a[0]), "r"(a[1]), "r"(a[2]), "r"(a[3]), "r"(b0), "r"(b1));
}

// ---------------------------------------------------------------------------
// Init kernels
__global__ void k_init_hs(const int* __restrict__ sidx, const int* __restrict__ ext,
                          const float* __restrict__ st, const float* __restrict__ et,
                          float* __restrict__ hs) {
    int t = blockIdx.x * blockDim.x + threadIdx.x;
    int row = t >> 5, c = t & 31;
    if (row >= NSP) return;
    int si = sidx[row], ei = ext[row];
    float4 a = ((const float4*)st)[si * 32 + c];
    float4 b = ((const float4*)et)[ei * 32 + c];
    float4 o;
    o.x = a.x + b.x; o.y = a.y + b.y; o.z = a.z + b.z; o.w = a.w + b.w;
    ((float4*)hs)[row * 32 + c] = o;
}

__global__ void k_init_hr(const int* __restrict__ tids, const float* __restrict__ params,
                          const float* __restrict__ tt, const float* __restrict__ Wp,
                          const float* __restrict__ bp, float* __restrict__ hr) {
    int t = blockIdx.x * blockDim.x + threadIdx.x;
    int row = t >> 5, c = t & 31;
    if (row >= NRX) return;
    int ti = tids[row];
    float4 acc = ((const float4*)tt)[ti * 32 + c];
    float4 bb  = ((const float4*)bp)[c];
    acc.x += bb.x; acc.y += bb.y; acc.z += bb.z; acc.w += bb.w;
#pragma unroll
    for (int k = 0; k < 8; k++) {
        float p = params[row * 8 + k];
        float4 w = ((const float4*)Wp)[k * 32 + c];
        acc.x += p * w.x; acc.y += p * w.y; acc.z += p * w.z; acc.w += p * w.w;
    }
    ((float4*)hr)[row * 32 + c] = acc;
}

// ---------------------------------------------------------------------------
// Segment sum, 4 edges per warp for MLP: dst[ed[e]] += src[es[e]]
__global__ void k_seg4(const float* __restrict__ src, float* __restrict__ dst,
                       const int* __restrict__ es, const int* __restrict__ ed) {
    int t = blockIdx.x * blockDim.x + threadIdx.x;
    int w = t >> 5, lane = t & 31;
    int e0 = w * 4;
    if (e0 >= NED) return;
    int4 s4 = *(const int4*)(es + e0);
    int4 d4 = *(const int4*)(ed + e0);
    const float4* src4 = (const float4*)src;
    float4 v0 = src4[(size_t)s4.x * 32 + lane];
    float4 v1 = src4[(size_t)s4.y * 32 + lane];
    float4 v2 = src4[(size_t)s4.z * 32 + lane];
    float4 v3 = src4[(size_t)s4.w * 32 + lane];
    float* p0 = dst + (size_t)d4.x * DM + lane * 4;
    float* p1 = dst + (size_t)d4.y * DM + lane * 4;
    float* p2 = dst + (size_t)d4.z * DM + lane * 4;
    float* p3 = dst + (size_t)d4.w * DM + lane * 4;
    asm volatile("red.global.add.v4.f32 [%0], {%1, %2, %3, %4};"
                 :: "l"(p0), "f"(v0.x), "f"(v0.y), "f"(v0.z), "f"(v0.w) : "memory");
    asm volatile("red.global.add.v4.f32 [%0], {%1, %2, %3, %4};"
                 :: "l"(p1), "f"(v1.x), "f"(v1.y), "f"(v1.z), "f"(v1.w) : "memory");
    asm volatile("red.global.add.v4.f32 [%0], {%1, %2, %3, %4};"
                 :: "l"(p2), "f"(v2.x), "f"(v2.y), "f"(v2.z), "f"(v2.w) : "memory");
    asm volatile("red.global.add.v4.f32 [%0], {%1, %2, %3, %4};"
                 :: "l"(p3), "f"(v3.x), "f"(v3.y), "f"(v3.z), "f"(v3.w) : "memory");
}

// ---------------------------------------------------------------------------
// W prep: transpose to [n][k], fp16.  l order: 0=Wr[0], 1=Ws[0], 2=Wr[1], 3=Ws[1]
__global__ void k_prep_w(const float* __restrict__ Wr, const float* __restrict__ Ws) {
    int idx = blockIdx.x * blockDim.x + threadIdx.x;
    if (idx >= 4 * 256 * 128) return;
    int l = idx >> 15;
    int rem = idx & 32767;
    int k = rem >> 7, n = rem & 127;
    const float* src = (l & 1) ? (Ws + (size_t)(l >> 1) * 2 * DM * DM)
                               : (Wr + (size_t)(l >> 1) * 2 * DM * DM);
    g_wt[l][n * 256 + k] = __float2half(src[k * DM + n]);
}

// ---------------------------------------------------------------------------
// fp16 tensor-core GEMM (K=128):  D[row] = relu?(X[row]) @ W[koff:koff+128] (+ bias)
// 256 threads (8 warps), CTA tile 128x128, warp tile 32x64, 2 CTAs/SM.
#define PITCH 72                 // halfs per smem row; 144B = 9*16B (16B-aligned rows)
#define PB    (PITCH * 2)
#define TILEB (128 * PB)         // 18432 B per tile

template<bool RELU_IN, bool HAS_BIAS>
__global__ void __launch_bounds__(256, 2) k_gemm_mma(
    float* __restrict__ D, const float* __restrict__ X,
    const __half* __restrict__ Wt, const float* __restrict__ bias, int n, int koff)
{
    extern __shared__ char sm[];
    char* pX = sm;
    char* pW = sm + TILEB;
    uint32_t aX = smem_u32(pX), aW = smem_u32(pW);

    int tid = threadIdx.x;
    int lane = tid & 31, wid = tid >> 5;
    int wm = (wid & 3) * 32;
    int wn = (wid >> 2) * 64;
    int rowBase = blockIdx.x * 128;

    // ldmatrix lane-address offsets (bytes within a tile)
    uint32_t aOff = (uint32_t)(wm + (lane & 15)) * PB + ((lane >> 4) * 8) * 2;
    uint32_t bOff = (uint32_t)(wn + (lane & 7) + ((lane >> 4) & 1) * 8) * PB
                  + (((lane >> 3) & 1) * 8) * 2;

    float acc[2][8][4];
#pragma unroll
    for (int mt = 0; mt < 2; mt++)
#pragma unroll
        for (int nt = 0; nt < 8; nt++)
#pragma unroll
            for (int j = 0; j < 4; j++) acc[mt][nt][j] = 0.f;

#pragma unroll
    for (int ch = 0; ch < 2; ch++) {
        int kq = ch * 16;
        // ---- X chunk: 128 rows x 64 k fp32 -> (relu) -> fp16 ----
#pragma unroll
        for (int i = 0; i < 8; i++) {
            int f = i * 256 + tid;
            int r = f >> 4, c = f & 15;
            int gr = rowBase + r;
            float4 v = make_float4(0.f, 0.f, 0.f, 0.f);
            if (gr < n) v = ((const float4*)X)[gr * 32 + kq + c];
            if (RELU_IN) {
                v.x = fmaxf(v.x, 0.f); v.y = fmaxf(v.y, 0.f);
                v.z = fmaxf(v.z, 0.f); v.w = fmaxf(v.w, 0.f);
            }
            __half2 h01 = __floats2half2_rn(v.x, v.y);
            __half2 h23 = __floats2half2_rn(v.z, v.w);
            uint32_t off = (uint32_t)r * PB + c * 8;
            *(uint32_t*)(pX + off)     = *(uint32_t*)&h01;
            *(uint32_t*)(pX + off + 4) = *(uint32_t*)&h23;
        }
        // ---- W chunk: 128 n x 64 k fp16 (pre-transposed) ----
#pragma unroll
        for (int i = 0; i < 4; i++) {
            int f = i * 256 + tid;
            int r = f >> 3, c = f & 7;
            size_t goff = (size_t)r * 256 + koff + ch * 64 + c * 8;
            uint32_t off = (uint32_t)r * PB + c * 16;
            *(uint4*)(pW + off) = *(const uint4*)(Wt + goff);
        }
        __syncthreads();

        // ---- 4 k16-steps ----
#pragma unroll
        for (int ks = 0; ks < 4; ks++) {
            uint32_t aF[2][4];
            ldsm4(aF[0], aX + aOff + ks * 32);
            ldsm4(aF[1], aX + aOff + ks * 32 + 16 * PB);
            uint32_t bF[4][4];
#pragma unroll
            for (int q = 0; q < 4; q++)
                ldsm4(bF[q], aW + bOff + ks * 32 + q * 16 * PB);
#pragma unroll
            for (int mt = 0; mt < 2; mt++)
#pragma unroll
                for (int q = 0; q < 4; q++) {
                    mma16816(acc[mt][q * 2 + 0], aF[mt], bF[q][0], bF[q][1]);
                    mma16816(acc[mt][q * 2 + 1], aF[mt], bF[q][2], bF[q][3]);
                }
        }
        __syncthreads();
    }

    // ---- epilogue: (+bias), NO relu (deferred to consumers) ----
    int r0 = (lane >> 2);
    int c0 = (lane & 3) * 2;
#pragma unroll
    for (int mt = 0; mt < 2; mt++) {
#pragma unroll
        for (int nt = 0; nt < 8; nt++) {
            int col = wn + nt * 8 + c0;
            float2 b2 = make_float2(0.f, 0.f);
            if (HAS_BIAS) b2 = *(const float2*)&bias[col];
            int rowA = rowBase + wm + mt * 16 + r0;
            int rowB = rowA + 8;
            if (rowA < n) {
                float2 o;
                o.x = acc[mt][nt][0] + b2.x;
                o.y = acc[mt][nt][1] + b2.y;
                *(float2*)&D[(size_t)rowA * DM + col] = o;
            }
            if (rowB < n) {
                float2 o;
                o.x = acc[mt][nt][2] + b2.x;
                o.y = acc[mt][nt][3] + b2.y;
                *(float2*)&D[(size_t)rowB * DM + col] = o;
            }
        }
    }
}

// ---------------------------------------------------------------------------
// Pool with deferred relu on inputs
__global__ void k_pool(const float* __restrict__ hs, const float* __restrict__ hr,
                       float* __restrict__ out) {
    int kind = blockIdx.z;
    int b = blockIdx.y;
    int col = blockIdx.x * 32 + (threadIdx.x & 31);
    int g = threadIdx.x >> 5;
    const float* h = kind ? hr : hs;
    int np = kind ? NR_PER : NS_PER;
    float inv = kind ? (1.f / NR_PER) : (1.f / NS_PER);
    size_t base = (size_t)b * np * DM;
    float s = 0.f;
    for (int i = g; i < np; i += 8)
        s += fmaxf(h[base + (size_t)i * DM + col], 0.f);
    __shared__ float red[8][32];
    red[g][threadIdx.x & 31] = s;
    __syncthreads();
    if (g == 0) {
        float tot = 0.f;
#pragma unroll
        for (int j = 0; j < 8; j++) tot += red[j][threadIdx.x & 31];
        out[b * 256 + kind * 128 + col] = tot * inv;
    }
}

// ---------------------------------------------------------------------------
extern "C" void kernel_launch(void* const* d_in, const int* in_sizes, int n_in,
                              void* d_out, int out_size) {
    const int*   species_indices = (const int*)  d_in[0];
    const int*   is_external     = (const int*)  d_in[1];
    const int*   prop_type_ids   = (const int*)  d_in[2];
    const float* prop_params     = (const float*)d_in[3];
    const int*   edge_species    = (const int*)  d_in[4];
    const int*   edge_reaction   = (const int*)  d_in[5];
    const float* species_table   = (const float*)d_in[8];
    const float* external_table  = (const float*)d_in[9];
    const float* type_table      = (const float*)d_in[10];
    const float* W_param         = (const float*)d_in[11];
    const float* b_param         = (const float*)d_in[12];
    const float* Wr              = (const float*)d_in[13];
    const float* br              = (const float*)d_in[14];
    const float* Ws              = (const float*)d_in[15];
    const float* bs              = (const float*)d_in[16];
    float* out = (float*)d_out;

    float *hsA, *hsB, *hrA, *hrB, *y, *z;
    __half* wt;
    cudaGetSymbolAddress((void**)&hsA, g_hsA);
    cudaGetSymbolAddress((void**)&hsB, g_hsB);
    cudaGetSymbolAddress((void**)&hrA, g_hrA);
    cudaGetSymbolAddress((void**)&hrB, g_hrB);
    cudaGetSymbolAddress((void**)&y, g_y);
    cudaGetSymbolAddress((void**)&z, g_z);
    cudaGetSymbolAddress((void**)&wt, g_wt);

    const int GEMM_SMEM = 2 * TILEB;   // 36864 B
    cudaFuncSetAttribute(k_gemm_mma<false, false>, cudaFuncAttributeMaxDynamicSharedMemorySize, GEMM_SMEM);
    cudaFuncSetAttribute(k_gemm_mma<false, true>,  cudaFuncAttributeMaxDynamicSharedMemorySize, GEMM_SMEM);
    cudaFuncSetAttribute(k_gemm_mma<true, false>,  cudaFuncAttributeMaxDynamicSharedMemorySize, GEMM_SMEM);
    cudaFuncSetAttribute(k_gemm_mma<true, true>,   cudaFuncAttributeMaxDynamicSharedMemorySize, GEMM_SMEM);

    k_init_hs<<<(NSP * 32 + 255) / 256, 256>>>(species_indices, is_external,
                                               species_table, external_table, hsA);
    k_init_hr<<<(NRX * 32 + 255) / 256, 256>>>(prop_type_ids, prop_params,
                                               type_table, W_param, b_param, hrA);
    k_prep_w<<<512, 256>>>(Wr, Ws);

    const int segBlocks = (NED / 4 * 32 + 255) / 256;   // 31250
    const int gS = (NSP + 127) / 128, gR = (NRX + 127) / 128;
    const size_t WSZ = (size_t)128 * 256;

    // ---- layer 0 (inputs have no relu) ----
    {
        const __half* Wr0 = wt + 0 * WSZ;
        const __half* Ws0 = wt + 1 * WSZ;
        k_gemm_mma<false, false><<<gS, 256, GEMM_SMEM>>>(y,   hsA, Wr0, nullptr, NSP, 128);
        k_gemm_mma<false, true ><<<gR, 256, GEMM_SMEM>>>(hrB, hrA, Wr0, br,      NRX, 0);
        k_seg4<<<segBlocks, 256>>>(y, hrB, edge_species, edge_reaction);
        k_gemm_mma<true,  false><<<gR, 256, GEMM_SMEM>>>(z,   hrB, Ws0, nullptr, NRX, 128);
        k_gemm_mma<false, true ><<<gS, 256, GEMM_SMEM>>>(hsB, hsA, Ws0, bs,      NSP, 0);
        k_seg4<<<segBlocks, 256>>>(z, hsB, edge_reaction, edge_species);
    }
    // ---- layer 1 (inputs need relu) ----
    {
        const __half* Wr1 = wt + 2 * WSZ;
        const __half* Ws1 = wt + 3 * WSZ;
        const float* br1 = br + DM;
        const float* bs1 = bs + DM;
        k_gemm_mma<true, false><<<gS, 256, GEMM_SMEM>>>(y,   hsB, Wr1, nullptr, NSP, 128);
        k_gemm_mma<true, true ><<<gR, 256, GEMM_SMEM>>>(hrA, hrB, Wr1, br1,     NRX, 0);
        k_seg4<<<segBlocks, 256>>>(y, hrA, edge_species, edge_reaction);
        k_gemm_mma<true, false><<<gR, 256, GEMM_SMEM>>>(z,   hrA, Ws1, nullptr, NRX, 128);
        k_gemm_mma<true, true ><<<gS, 256, GEMM_SMEM>>>(hsA, hsB, Ws1, bs1,     NSP, 0);
        k_seg4<<<segBlocks, 256>>>(z, hsA, edge_reaction, edge_species);
    }

    k_pool<<<dim3(4, BGR, 2), 256>>>(hsA, hrA, out);
}

// round 7
// speedup vs baseline: 1.4789x; 1.1291x over previous
#include <cuda_runtime.h>
#include <cuda_fp16.h>
#include <cstdint>

#define NSP 100000
#define NRX 200000
#define NED 1000000
#define DM  128
#define BGR 50
#define NS_PER 2000
#define NR_PER 4000

// Scratch buffers (static device globals)
__device__ float g_hsA[NSP * DM];
__device__ float g_hsB[NSP * DM];
__device__ float g_hrA[NRX * DM];
__device__ float g_hrB[NRX * DM];
__device__ __half g_y[NSP * DM];   // Y = relu?(h_s) @ Wr2   (fp16 messages)
__device__ __half g_z[NRX * DM];   // Z = relu(h_r)  @ Ws2
// Pre-transposed fp16 weights: [which of 4][n=128][k=256]
__device__ __half g_wt[4][128 * 256];

// ---------------------------------------------------------------------------
__device__ __forceinline__ uint32_t smem_u32(const void* p) {
    uint32_t a;
    asm("{ .reg .u64 t; cvta.to.shared.u64 t, %1; cvt.u32.u64 %0, t; }" : "=r"(a) : "l"(p));
    return a;
}
__device__ __forceinline__ void ldsm4(uint32_t r[4], uint32_t addr) {
    asm volatile("ldmatrix.sync.aligned.m8n8.x4.shared.b16 {%0,%1,%2,%3}, [%4];"
                 : "=r"(r[0]), "=r"(r[1]), "=r"(r[2]), "=r"(r[3]) : "r"(addr));
}
__device__ __forceinline__ void mma16816(float c[4], const uint32_t a[4],
                                         uint32_t b0, uint32_t b1) {
    asm volatile(
        "mma.sync.aligned.m16n8k16.row.col.f32.f16.f16.f32 "
        "{%0,%1,%2,%3}, {%4,%5,%6,%7}, {%8,%9}, {%0,%1,%2,%3};"
        : "+f"(c[0]), "+f"(c[1]), "+f"(c[2]), "+f"(c[3])
        : "r"(a[0]), "r"(a[1]), "r"(a[2]), "r"(a[3]), "r"(b0), "r"(b1));
}

// ---------------------------------------------------------------------------
// Init kernels
__global__ void k_init_hs(const int* __restrict__ sidx, const int* __restrict__ ext,
                          const float* __restrict__ st, const float* __restrict__ et,
                          float* __restrict__ hs) {
    int t = blockIdx.x * blockDim.x + threadIdx.x;
    int row = t >> 5, c = t & 31;
    if (row >= NSP) return;
    int si = sidx[row], ei = ext[row];
    float4 a = ((const float4*)st)[si * 32 + c];
    float4 b = ((const float4*)et)[ei * 32 + c];
    float4 o;
    o.x = a.x + b.x; o.y = a.y + b.y; o.z = a.z + b.z; o.w = a.w + b.w;
    ((float4*)hs)[row * 32 + c] = o;
}

__global__ void k_init_hr(const int* __restrict__ tids, const float* __restrict__ params,
                          const float* __restrict__ tt, const float* __restrict__ Wp,
                          const float* __restrict__ bp, float* __restrict__ hr) {
    int t = blockIdx.x * blockDim.x + threadIdx.x;
    int row = t >> 5, c = t & 31;
    if (row >= NRX) return;
    int ti = tids[row];
    float4 acc = ((const float4*)tt)[ti * 32 + c];
    float4 bb  = ((const float4*)bp)[c];
    acc.x += bb.x; acc.y += bb.y; acc.z += bb.z; acc.w += bb.w;
#pragma unroll
    for (int k = 0; k < 8; k++) {
        float p = params[row * 8 + k];
        float4 w = ((const float4*)Wp)[k * 32 + c];
        acc.x += p * w.x; acc.y += p * w.y; acc.z += p * w.z; acc.w += p * w.w;
    }
    ((float4*)hr)[row * 32 + c] = acc;
}

// ---------------------------------------------------------------------------
// Segment sum, 8 edges per warp, fp16 source rows, fp32 RED accumulation.
// dst[ed[e]] += (float)src[es[e]]
__global__ void k_seg8(const __half* __restrict__ src, float* __restrict__ dst,
                       const int* __restrict__ es, const int* __restrict__ ed) {
    int t = blockIdx.x * blockDim.x + threadIdx.x;
    int w = t >> 5, lane = t & 31;
    int e0 = w * 8;
    if (e0 >= NED) return;
    int4 sa = *(const int4*)(es + e0);
    int4 sb = *(const int4*)(es + e0 + 4);
    int4 da = *(const int4*)(ed + e0);
    int4 db = *(const int4*)(ed + e0 + 4);
    int sI[8] = {sa.x, sa.y, sa.z, sa.w, sb.x, sb.y, sb.z, sb.w};
    int dI[8] = {da.x, da.y, da.z, da.w, db.x, db.y, db.z, db.w};
    uint2 v[8];
#pragma unroll
    for (int i = 0; i < 8; i++)
        v[i] = ((const uint2*)(src + (size_t)sI[i] * DM))[lane];   // 4 halfs
#pragma unroll
    for (int i = 0; i < 8; i++) {
        __half2 h01 = *(__half2*)&v[i].x;
        __half2 h23 = *(__half2*)&v[i].y;
        float2 f01 = __half22float2(h01);
        float2 f23 = __half22float2(h23);
        float* p = dst + (size_t)dI[i] * DM + lane * 4;
        asm volatile("red.global.add.v4.f32 [%0], {%1, %2, %3, %4};"
                     :: "l"(p), "f"(f01.x), "f"(f01.y), "f"(f23.x), "f"(f23.y)
                     : "memory");
    }
}

// ---------------------------------------------------------------------------
// W prep: transpose to [n][k], fp16.  l order: 0=Wr[0], 1=Ws[0], 2=Wr[1], 3=Ws[1]
__global__ void k_prep_w(const float* __restrict__ Wr, const float* __restrict__ Ws) {
    int idx = blockIdx.x * blockDim.x + threadIdx.x;
    if (idx >= 4 * 256 * 128) return;
    int l = idx >> 15;
    int rem = idx & 32767;
    int k = rem >> 7, n = rem & 127;
    const float* src = (l & 1) ? (Ws + (size_t)(l >> 1) * 2 * DM * DM)
                               : (Wr + (size_t)(l >> 1) * 2 * DM * DM);
    g_wt[l][n * 256 + k] = __float2half(src[k * DM + n]);
}

// ---------------------------------------------------------------------------
// Paired fp16 tensor-core GEMM. Two independent jobs in one grid:
//   blocks [0, gA):      DA(half)  = relu?(XA) @ W[koffA..+128)            (message GEMM)
//   blocks [gA, gA+gB):  DB(float) = relu?(XB) @ W[koffB..+128) + biasB    (state GEMM)
// 256 threads (8 warps), CTA tile 128x128, warp tile 32x64, 2 CTAs/SM.
#define PITCH 72                 // halfs per smem row; 144B (16B-aligned rows)
#define PB    (PITCH * 2)
#define TILEB (128 * PB)         // 18432 B per tile

__global__ void __launch_bounds__(256, 2) k_gemm_pair(
    __half* __restrict__ DA, const float* __restrict__ XA,
    const __half* __restrict__ WtA, int nA, int koffA, int reluA, int gA,
    float* __restrict__ DB, const float* __restrict__ XB,
    const __half* __restrict__ WtB, const float* __restrict__ biasB,
    int nB, int koffB, int reluB)
{
    extern __shared__ char sm[];
    char* pX = sm;
    char* pW = sm + TILEB;
    uint32_t aX = smem_u32(pX), aW = smem_u32(pW);

    const bool jobB = ((int)blockIdx.x >= gA);
    const float* X = jobB ? XB : XA;
    const __half* Wt = jobB ? WtB : WtA;
    const int n     = jobB ? nB : nA;
    const int koff  = jobB ? koffB : koffA;
    const int relu  = jobB ? reluB : reluA;
    const int rowBase = (jobB ? ((int)blockIdx.x - gA) : (int)blockIdx.x) * 128;

    int tid = threadIdx.x;
    int lane = tid & 31, wid = tid >> 5;
    int wm = (wid & 3) * 32;
    int wn = (wid >> 2) * 64;

    uint32_t aOff = (uint32_t)(wm + (lane & 15)) * PB + ((lane >> 4) * 8) * 2;
    uint32_t bOff = (uint32_t)(wn + (lane & 7) + ((lane >> 4) & 1) * 8) * PB
                  + (((lane >> 3) & 1) * 8) * 2;

    float acc[2][8][4];
#pragma unroll
    for (int mt = 0; mt < 2; mt++)
#pragma unroll
        for (int nt = 0; nt < 8; nt++)
#pragma unroll
            for (int j = 0; j < 4; j++) acc[mt][nt][j] = 0.f;

#pragma unroll
    for (int ch = 0; ch < 2; ch++) {
        int kq = ch * 16;
        // ---- X chunk: 128 rows x 64 k fp32 -> (relu) -> fp16 ----
#pragma unroll
        for (int i = 0; i < 8; i++) {
            int f = i * 256 + tid;
            int r = f >> 4, c = f & 15;
            int gr = rowBase + r;
            float4 v = make_float4(0.f, 0.f, 0.f, 0.f);
            if (gr < n) v = ((const float4*)X)[gr * 32 + kq + c];
            if (relu) {
                v.x = fmaxf(v.x, 0.f); v.y = fmaxf(v.y, 0.f);
                v.z = fmaxf(v.z, 0.f); v.w = fmaxf(v.w, 0.f);
            }
            __half2 h01 = __floats2half2_rn(v.x, v.y);
            __half2 h23 = __floats2half2_rn(v.z, v.w);
            uint32_t off = (uint32_t)r * PB + c * 8;
            *(uint32_t*)(pX + off)     = *(uint32_t*)&h01;
            *(uint32_t*)(pX + off + 4) = *(uint32_t*)&h23;
        }
        // ---- W chunk: 128 n x 64 k fp16 (pre-transposed) ----
#pragma unroll
        for (int i = 0; i < 4; i++) {
            int f = i * 256 + tid;
            int r = f >> 3, c = f & 7;
            size_t goff = (size_t)r * 256 + koff + ch * 64 + c * 8;
            uint32_t off = (uint32_t)r * PB + c * 16;
            *(uint4*)(pW + off) = *(const uint4*)(Wt + goff);
        }
        __syncthreads();

        // ---- 4 k16-steps ----
#pragma unroll
        for (int ks = 0; ks < 4; ks++) {
            uint32_t aF[2][4];
            ldsm4(aF[0], aX + aOff + ks * 32);
            ldsm4(aF[1], aX + aOff + ks * 32 + 16 * PB);
            uint32_t bF[4][4];
#pragma unroll
            for (int q = 0; q < 4; q++)
                ldsm4(bF[q], aW + bOff + ks * 32 + q * 16 * PB);
#pragma unroll
            for (int mt = 0; mt < 2; mt++)
#pragma unroll
                for (int q = 0; q < 4; q++) {
                    mma16816(acc[mt][q * 2 + 0], aF[mt], bF[q][0], bF[q][1]);
                    mma16816(acc[mt][q * 2 + 1], aF[mt], bF[q][2], bF[q][3]);
                }
        }
        __syncthreads();
    }

    // ---- epilogue ----
    int r0 = (lane >> 2);
    int c0 = (lane & 3) * 2;
    if (!jobB) {
        // fp16 message output, no bias, no relu
#pragma unroll
        for (int mt = 0; mt < 2; mt++) {
#pragma unroll
            for (int nt = 0; nt < 8; nt++) {
                int col = wn + nt * 8 + c0;
                int rowA = rowBase + wm + mt * 16 + r0;
                int rowB = rowA + 8;
                if (rowA < n)
                    *(__half2*)&DA[(size_t)rowA * DM + col] =
                        __floats2half2_rn(acc[mt][nt][0], acc[mt][nt][1]);
                if (rowB < n)
                    *(__half2*)&DA[(size_t)rowB * DM + col] =
                        __floats2half2_rn(acc[mt][nt][2], acc[mt][nt][3]);
            }
        }
    } else {
        // fp32 state output + bias, relu deferred to consumers
#pragma unroll
        for (int mt = 0; mt < 2; mt++) {
#pragma unroll
            for (int nt = 0; nt < 8; nt++) {
                int col = wn + nt * 8 + c0;
                float2 b2 = *(const float2*)&biasB[col];
                int rowA = rowBase + wm + mt * 16 + r0;
                int rowB = rowA + 8;
                if (rowA < n) {
                    float2 o;
                    o.x = acc[mt][nt][0] + b2.x;
                    o.y = acc[mt][nt][1] + b2.y;
                    *(float2*)&DB[(size_t)rowA * DM + col] = o;
                }
                if (rowB < n) {
                    float2 o;
                    o.x = acc[mt][nt][2] + b2.x;
                    o.y = acc[mt][nt][3] + b2.y;
                    *(float2*)&DB[(size_t)rowB * DM + col] = o;
                }
            }
        }
    }
}

// ---------------------------------------------------------------------------
// Pool with deferred relu on inputs
__global__ void k_pool(const float* __restrict__ hs, const float* __restrict__ hr,
                       float* __restrict__ out) {
    int kind = blockIdx.z;
    int b = blockIdx.y;
    int col = blockIdx.x * 32 + (threadIdx.x & 31);
    int g = threadIdx.x >> 5;
    const float* h = kind ? hr : hs;
    int np = kind ? NR_PER : NS_PER;
    float inv = kind ? (1.f / NR_PER) : (1.f / NS_PER);
    size_t base = (size_t)b * np * DM;
    float s = 0.f;
    for (int i = g; i < np; i += 8)
        s += fmaxf(h[base + (size_t)i * DM + col], 0.f);
    __shared__ float red[8][32];
    red[g][threadIdx.x & 31] = s;
    __syncthreads();
    if (g == 0) {
        float tot = 0.f;
#pragma unroll
        for (int j = 0; j < 8; j++) tot += red[j][threadIdx.x & 31];
        out[b * 256 + kind * 128 + col] = tot * inv;
    }
}

// ---------------------------------------------------------------------------
extern "C" void kernel_launch(void* const* d_in, const int* in_sizes, int n_in,
                              void* d_out, int out_size) {
    const int*   species_indices = (const int*)  d_in[0];
    const int*   is_external     = (const int*)  d_in[1];
    const int*   prop_type_ids   = (const int*)  d_in[2];
    const float* prop_params     = (const float*)d_in[3];
    const int*   edge_species    = (const int*)  d_in[4];
    const int*   edge_reaction   = (const int*)  d_in[5];
    const float* species_table   = (const float*)d_in[8];
    const float* external_table  = (const float*)d_in[9];
    const float* type_table      = (const float*)d_in[10];
    const float* W_param         = (const float*)d_in[11];
    const float* b_param         = (const float*)d_in[12];
    const float* Wr              = (const float*)d_in[13];
    const float* br              = (const float*)d_in[14];
    const float* Ws              = (const float*)d_in[15];
    const float* bs              = (const float*)d_in[16];
    float* out = (float*)d_out;

    float *hsA, *hsB, *hrA, *hrB;
    __half *y, *z, *wt;
    cudaGetSymbolAddress((void**)&hsA, g_hsA);
    cudaGetSymbolAddress((void**)&hsB, g_hsB);
    cudaGetSymbolAddress((void**)&hrA, g_hrA);
    cudaGetSymbolAddress((void**)&hrB, g_hrB);
    cudaGetSymbolAddress((void**)&y, g_y);
    cudaGetSymbolAddress((void**)&z, g_z);
    cudaGetSymbolAddress((void**)&wt, g_wt);

    const int GEMM_SMEM = 2 * TILEB;   // 36864 B
    cudaFuncSetAttribute(k_gemm_pair, cudaFuncAttributeMaxDynamicSharedMemorySize, GEMM_SMEM);

    k_init_hs<<<(NSP * 32 + 255) / 256, 256>>>(species_indices, is_external,
                                               species_table, external_table, hsA);
    k_init_hr<<<(NRX * 32 + 255) / 256, 256>>>(prop_type_ids, prop_params,
                                               type_table, W_param, b_param, hrA);
    k_prep_w<<<512, 256>>>(Wr, Ws);

    const int segBlocks = (NED / 8 * 32) / 256;   // 15625
    const int gS = (NSP + 127) / 128, gR = (NRX + 127) / 128;
    const size_t WSZ = (size_t)128 * 256;
    const __half* Wr0 = wt + 0 * WSZ;
    const __half* Ws0 = wt + 1 * WSZ;
    const __half* Wr1 = wt + 2 * WSZ;
    const __half* Ws1 = wt + 3 * WSZ;

    // ---- layer 0 (inputs raw) ----
    k_gemm_pair<<<gS + gR, 256, GEMM_SMEM>>>(
        y,   hsA, Wr0, NSP, 128, 0, gS,
        hrB, hrA, Wr0, br,  NRX, 0, 0);
    k_seg8<<<segBlocks, 256>>>(y, hrB, edge_species, edge_reaction);
    k_gemm_pair<<<gR + gS, 256, GEMM_SMEM>>>(
        z,   hrB, Ws0, NRX, 128, 1, gR,
        hsB, hsA, Ws0, bs,  NSP, 0, 0);
    k_seg8<<<segBlocks, 256>>>(z, hsB, edge_reaction, edge_species);

    // ---- layer 1 (inputs need relu) ----
    k_gemm_pair<<<gS + gR, 256, GEMM_SMEM>>>(
        y,   hsB, Wr1, NSP, 128, 1, gS,
        hrA, hrB, Wr1, br + DM, NRX, 0, 1);
    k_seg8<<<segBlocks, 256>>>(y, hrA, edge_species, edge_reaction);
    k_gemm_pair<<<gR + gS, 256, GEMM_SMEM>>>(
        z,   hrA, Ws1, NRX, 128, 1, gR,
        hsA, hsB, Ws1, bs + DM, NSP, 0, 1);
    k_seg8<<<segBlocks, 256>>>(z, hsA, edge_reaction, edge_species);

    k_pool<<<dim3(4, BGR, 2), 256>>>(hsA, hrA, out);
}

// round 8
// speedup vs baseline: 1.9559x; 1.3225x over previous
#include <cuda_runtime.h>
#include <cuda_fp16.h>
#include <cstdint>

#define NSP 100000
#define NRX 200000
#define NED 1000000
#define DM  128
#define BGR 50
#define NS_PER 2000
#define NR_PER 4000

// State / message buffers — all fp16 now
__device__ __half g_hsA[NSP * DM];
__device__ __half g_hsB[NSP * DM];
__device__ __half g_hrA[NRX * DM];
__device__ __half g_hrB[NRX * DM];
__device__ __half g_y[NSP * DM];
__device__ __half g_z[NRX * DM];
// Pre-transposed fp16 weights: [which of 4][n=128][k=256]
__device__ __half g_wt[4][128 * 256];

// ---------------------------------------------------------------------------
__device__ __forceinline__ uint32_t smem_u32(const void* p) {
    uint32_t a;
    asm("{ .reg .u64 t; cvta.to.shared.u64 t, %1; cvt.u32.u64 %0, t; }" : "=r"(a) : "l"(p));
    return a;
}
__device__ __forceinline__ void ldsm4(uint32_t r[4], uint32_t addr) {
    asm volatile("ldmatrix.sync.aligned.m8n8.x4.shared.b16 {%0,%1,%2,%3}, [%4];"
                 : "=r"(r[0]), "=r"(r[1]), "=r"(r[2]), "=r"(r[3]) : "r"(addr));
}
__device__ __forceinline__ void mma16816(float c[4], const uint32_t a[4],
                                         uint32_t b0, uint32_t b1) {
    asm volatile(
        "mma.sync.aligned.m16n8k16.row.col.f32.f16.f16.f32 "
        "{%0,%1,%2,%3}, {%4,%5,%6,%7}, {%8,%9}, {%0,%1,%2,%3};"
        : "+f"(c[0]), "+f"(c[1]), "+f"(c[2]), "+f"(c[3])
        : "r"(a[0]), "r"(a[1]), "r"(a[2]), "r"(a[3]), "r"(b0), "r"(b1));
}

// ---------------------------------------------------------------------------
// Init kernels — write fp16 states
__global__ void k_init_hs(const int* __restrict__ sidx, const int* __restrict__ ext,
                          const float* __restrict__ st, const float* __restrict__ et,
                          __half* __restrict__ hs) {
    int t = blockIdx.x * blockDim.x + threadIdx.x;
    int row = t >> 5, c = t & 31;
    if (row >= NSP) return;
    int si = sidx[row], ei = ext[row];
    float4 a = ((const float4*)st)[si * 32 + c];
    float4 b = ((const float4*)et)[ei * 32 + c];
    __half2 o01 = __floats2half2_rn(a.x + b.x, a.y + b.y);
    __half2 o23 = __floats2half2_rn(a.z + b.z, a.w + b.w);
    uint2 o;
    o.x = *(uint32_t*)&o01; o.y = *(uint32_t*)&o23;
    ((uint2*)hs)[row * 32 + c] = o;
}

__global__ void k_init_hr(const int* __restrict__ tids, const float* __restrict__ params,
                          const float* __restrict__ tt, const float* __restrict__ Wp,
                          const float* __restrict__ bp, __half* __restrict__ hr) {
    int t = blockIdx.x * blockDim.x + threadIdx.x;
    int row = t >> 5, c = t & 31;
    if (row >= NRX) return;
    int ti = tids[row];
    float4 acc = ((const float4*)tt)[ti * 32 + c];
    float4 bb  = ((const float4*)bp)[c];
    acc.x += bb.x; acc.y += bb.y; acc.z += bb.z; acc.w += bb.w;
#pragma unroll
    for (int k = 0; k < 8; k++) {
        float p = params[row * 8 + k];
        float4 w = ((const float4*)Wp)[k * 32 + c];
        acc.x += p * w.x; acc.y += p * w.y; acc.z += p * w.z; acc.w += p * w.w;
    }
    __half2 o01 = __floats2half2_rn(acc.x, acc.y);
    __half2 o23 = __floats2half2_rn(acc.z, acc.w);
    uint2 o;
    o.x = *(uint32_t*)&o01; o.y = *(uint32_t*)&o23;
    ((uint2*)hr)[row * 32 + c] = o;
}

// ---------------------------------------------------------------------------
// Segment sum, 8 edges per warp, fp16 rows, fp16x2 vector RED accumulation.
// dst[ed[e]] += src[es[e]]   (both fp16; lane handles 4 halfs = 8B)
__global__ void k_seg8(const __half* __restrict__ src, __half* __restrict__ dst,
                       const int* __restrict__ es, const int* __restrict__ ed) {
    int t = blockIdx.x * blockDim.x + threadIdx.x;
    int w = t >> 5, lane = t & 31;
    int e0 = w * 8;
    if (e0 >= NED) return;
    int4 sa = *(const int4*)(es + e0);
    int4 sb = *(const int4*)(es + e0 + 4);
    int4 da = *(const int4*)(ed + e0);
    int4 db = *(const int4*)(ed + e0 + 4);
    int sI[8] = {sa.x, sa.y, sa.z, sa.w, sb.x, sb.y, sb.z, sb.w};
    int dI[8] = {da.x, da.y, da.z, da.w, db.x, db.y, db.z, db.w};
    uint2 v[8];
#pragma unroll
    for (int i = 0; i < 8; i++)
        v[i] = ((const uint2*)(src + (size_t)sI[i] * DM))[lane];
#pragma unroll
    for (int i = 0; i < 8; i++) {
        __half* p = dst + (size_t)dI[i] * DM + lane * 4;
        asm volatile("red.global.add.noftz.v2.f16x2 [%0], {%1, %2};"
                     :: "l"(p), "r"(v[i].x), "r"(v[i].y) : "memory");
    }
}

// ---------------------------------------------------------------------------
// W prep: transpose to [n][k], fp16.  l order: 0=Wr[0], 1=Ws[0], 2=Wr[1], 3=Ws[1]
__global__ void k_prep_w(const float* __restrict__ Wr, const float* __restrict__ Ws) {
    int idx = blockIdx.x * blockDim.x + threadIdx.x;
    if (idx >= 4 * 256 * 128) return;
    int l = idx >> 15;
    int rem = idx & 32767;
    int k = rem >> 7, n = rem & 127;
    const float* src = (l & 1) ? (Ws + (size_t)(l >> 1) * 2 * DM * DM)
                               : (Wr + (size_t)(l >> 1) * 2 * DM * DM);
    g_wt[l][n * 256 + k] = __float2half(src[k * DM + n]);
}

// ---------------------------------------------------------------------------
// Paired fp16 tensor-core GEMM, fp16 in / fp16 out. Two jobs per grid:
//   blocks [0, gA):      DA = relu?(XA) @ W[koffA..+128)           (message GEMM)
//   blocks [gA, gA+gB):  DB = relu?(XB) @ W[koffB..+128) + biasB   (state GEMM)
// 256 threads (8 warps), CTA tile 128x128, warp tile 32x64, 2 CTAs/SM.
#define PITCH 72
#define PB    (PITCH * 2)
#define TILEB (128 * PB)

__global__ void __launch_bounds__(256, 2) k_gemm_pair(
    __half* __restrict__ DA, const __half* __restrict__ XA,
    const __half* __restrict__ WtA, int nA, int koffA, int reluA, int gA,
    __half* __restrict__ DB, const __half* __restrict__ XB,
    const __half* __restrict__ WtB, const float* __restrict__ biasB,
    int nB, int koffB, int reluB)
{
    extern __shared__ char sm[];
    char* pX = sm;
    char* pW = sm + TILEB;
    uint32_t aX = smem_u32(pX), aW = smem_u32(pW);

    const bool jobB = ((int)blockIdx.x >= gA);
    const __half* X = jobB ? XB : XA;
    const __half* Wt = jobB ? WtB : WtA;
    const int n     = jobB ? nB : nA;
    const int koff  = jobB ? koffB : koffA;
    const int relu  = jobB ? reluB : reluA;
    const int rowBase = (jobB ? ((int)blockIdx.x - gA) : (int)blockIdx.x) * 128;

    int tid = threadIdx.x;
    int lane = tid & 31, wid = tid >> 5;
    int wm = (wid & 3) * 32;
    int wn = (wid >> 2) * 64;

    uint32_t aOff = (uint32_t)(wm + (lane & 15)) * PB + ((lane >> 4) * 8) * 2;
    uint32_t bOff = (uint32_t)(wn + (lane & 7) + ((lane >> 4) & 1) * 8) * PB
                  + (((lane >> 3) & 1) * 8) * 2;

    float acc[2][8][4];
#pragma unroll
    for (int mt = 0; mt < 2; mt++)
#pragma unroll
        for (int nt = 0; nt < 8; nt++)
#pragma unroll
            for (int j = 0; j < 4; j++) acc[mt][nt][j] = 0.f;

    const __half2 z2 = __float2half2_rn(0.f);

#pragma unroll
    for (int ch = 0; ch < 2; ch++) {
        // ---- X chunk: 128 rows x 64 k fp16 (relu in fp16) ----
#pragma unroll
        for (int i = 0; i < 4; i++) {
            int f = i * 256 + tid;
            int r = f >> 3, c = f & 7;
            int gr = rowBase + r;
            uint4 v = make_uint4(0u, 0u, 0u, 0u);
            if (gr < n) v = *(const uint4*)(X + (size_t)gr * DM + ch * 64 + c * 8);
            if (relu) {
                *(__half2*)&v.x = __hmax2(*(__half2*)&v.x, z2);
                *(__half2*)&v.y = __hmax2(*(__half2*)&v.y, z2);
                *(__half2*)&v.z = __hmax2(*(__half2*)&v.z, z2);
                *(__half2*)&v.w = __hmax2(*(__half2*)&v.w, z2);
            }
            *(uint4*)(pX + (uint32_t)r * PB + c * 16) = v;
        }
        // ---- W chunk: 128 n x 64 k fp16 (pre-transposed) ----
#pragma unroll
        for (int i = 0; i < 4; i++) {
            int f = i * 256 + tid;
            int r = f >> 3, c = f & 7;
            size_t goff = (size_t)r * 256 + koff + ch * 64 + c * 8;
            *(uint4*)(pW + (uint32_t)r * PB + c * 16) = *(const uint4*)(Wt + goff);
        }
        __syncthreads();

        // ---- 4 k16-steps ----
#pragma unroll
        for (int ks = 0; ks < 4; ks++) {
            uint32_t aF[2][4];
            ldsm4(aF[0], aX + aOff + ks * 32);
            ldsm4(aF[1], aX + aOff + ks * 32 + 16 * PB);
            uint32_t bF[4][4];
#pragma unroll
            for (int q = 0; q < 4; q++)
                ldsm4(bF[q], aW + bOff + ks * 32 + q * 16 * PB);
#pragma unroll
            for (int mt = 0; mt < 2; mt++)
#pragma unroll
                for (int q = 0; q < 4; q++) {
                    mma16816(acc[mt][q * 2 + 0], aF[mt], bF[q][0], bF[q][1]);
                    mma16816(acc[mt][q * 2 + 1], aF[mt], bF[q][2], bF[q][3]);
                }
        }
        __syncthreads();
    }

    // ---- epilogue: fp16 output; jobB adds bias (fp32) first ----
    int r0 = (lane >> 2);
    int c0 = (lane & 3) * 2;
    __half* D = jobB ? DB : DA;
#pragma unroll
    for (int mt = 0; mt < 2; mt++) {
#pragma unroll
        for (int nt = 0; nt < 8; nt++) {
            int col = wn + nt * 8 + c0;
            float2 b2 = make_float2(0.f, 0.f);
            if (jobB) b2 = *(const float2*)&biasB[col];
            int rowA = rowBase + wm + mt * 16 + r0;
            int rowB = rowA + 8;
            if (rowA < n)
                *(__half2*)&D[(size_t)rowA * DM + col] =
                    __floats2half2_rn(acc[mt][nt][0] + b2.x, acc[mt][nt][1] + b2.y);
            if (rowB < n)
                *(__half2*)&D[(size_t)rowB * DM + col] =
                    __floats2half2_rn(acc[mt][nt][2] + b2.x, acc[mt][nt][3] + b2.y);
        }
    }
}

// ---------------------------------------------------------------------------
// Pool: fp16 states, relu on load, fp32 accumulation.
// grid (2, BGR, 2): blockIdx.x selects 32 half2-cols; 8 warps stride rows.
__global__ void k_pool(const __half* __restrict__ hs, const __half* __restrict__ hr,
                       float* __restrict__ out) {
    int kind = blockIdx.z;
    int b = blockIdx.y;
    int lane = threadIdx.x & 31;
    int g = threadIdx.x >> 5;
    int col2 = blockIdx.x * 32 + lane;      // half2 column index (0..63)
    const __half* h = kind ? hr : hs;
    int np = kind ? NR_PER : NS_PER;
    float inv = kind ? (1.f / NR_PER) : (1.f / NS_PER);
    size_t base2 = (size_t)b * np * 64;     // in half2 units
    const __half2* h2 = (const __half2*)h;
    float sx = 0.f, sy = 0.f;
    for (int i = g; i < np; i += 8) {
        float2 f = __half22float2(h2[base2 + (size_t)i * 64 + col2]);
        sx += fmaxf(f.x, 0.f);
        sy += fmaxf(f.y, 0.f);
    }
    __shared__ float red[8][64];
    red[g][lane * 2]     = sx;
    red[g][lane * 2 + 1] = sy;
    __syncthreads();
    if (g == 0) {
        float tx = 0.f, ty = 0.f;
#pragma unroll
        for (int j = 0; j < 8; j++) { tx += red[j][lane * 2]; ty += red[j][lane * 2 + 1]; }
        int col = col2 * 2;
        out[b * 256 + kind * 128 + col]     = tx * inv;
        out[b * 256 + kind * 128 + col + 1] = ty * inv;
    }
}

// ---------------------------------------------------------------------------
extern "C" void kernel_launch(void* const* d_in, const int* in_sizes, int n_in,
                              void* d_out, int out_size) {
    const int*   species_indices = (const int*)  d_in[0];
    const int*   is_external     = (const int*)  d_in[1];
    const int*   prop_type_ids   = (const int*)  d_in[2];
    const float* prop_params     = (const float*)d_in[3];
    const int*   edge_species    = (const int*)  d_in[4];
    const int*   edge_reaction   = (const int*)  d_in[5];
    const float* species_table   = (const float*)d_in[8];
    const float* external_table  = (const float*)d_in[9];
    const float* type_table      = (const float*)d_in[10];
    const float* W_param         = (const float*)d_in[11];
    const float* b_param         = (const float*)d_in[12];
    const float* Wr              = (const float*)d_in[13];
    const float* br              = (const float*)d_in[14];
    const float* Ws              = (const float*)d_in[15];
    const float* bs              = (const float*)d_in[16];
    float* out = (float*)d_out;

    __half *hsA, *hsB, *hrA, *hrB, *y, *z, *wt;
    cudaGetSymbolAddress((void**)&hsA, g_hsA);
    cudaGetSymbolAddress((void**)&hsB, g_hsB);
    cudaGetSymbolAddress((void**)&hrA, g_hrA);
    cudaGetSymbolAddress((void**)&hrB, g_hrB);
    cudaGetSymbolAddress((void**)&y, g_y);
    cudaGetSymbolAddress((void**)&z, g_z);
    cudaGetSymbolAddress((void**)&wt, g_wt);

    const int GEMM_SMEM = 2 * TILEB;   // 36864 B
    cudaFuncSetAttribute(k_gemm_pair, cudaFuncAttributeMaxDynamicSharedMemorySize, GEMM_SMEM);

    k_init_hs<<<(NSP * 32 + 255) / 256, 256>>>(species_indices, is_external,
                                               species_table, external_table, hsA);
    k_init_hr<<<(NRX * 32 + 255) / 256, 256>>>(prop_type_ids, prop_params,
                                               type_table, W_param, b_param, hrA);
    k_prep_w<<<512, 256>>>(Wr, Ws);

    const int segBlocks = (NED / 8 * 32) / 256;   // 15625
    const int gS = (NSP + 127) / 128, gR = (NRX + 127) / 128;
    const size_t WSZ = (size_t)128 * 256;
    const __half* Wr0 = wt + 0 * WSZ;
    const __half* Ws0 = wt + 1 * WSZ;
    const __half* Wr1 = wt + 2 * WSZ;
    const __half* Ws1 = wt + 3 * WSZ;

    // ---- layer 0 (inputs raw) ----
    k_gemm_pair<<<gS + gR, 256, GEMM_SMEM>>>(
        y,   hsA, Wr0, NSP, 128, 0, gS,
        hrB, hrA, Wr0, br,  NRX, 0, 0);
    k_seg8<<<segBlocks, 256>>>(y, hrB, edge_species, edge_reaction);
    k_gemm_pair<<<gR + gS, 256, GEMM_SMEM>>>(
        z,   hrB, Ws0, NRX, 128, 1, gR,
        hsB, hsA, Ws0, bs,  NSP, 0, 0);
    k_seg8<<<segBlocks, 256>>>(z, hsB, edge_reaction, edge_species);

    // ---- layer 1 (inputs need relu) ----
    k_gemm_pair<<<gS + gR, 256, GEMM_SMEM>>>(
        y,   hsB, Wr1, NSP, 128, 1, gS,
        hrA, hrB, Wr1, br + DM, NRX, 0, 1);
    k_seg8<<<segBlocks, 256>>>(y, hrA, edge_species, edge_reaction);
    k_gemm_pair<<<gR + gS, 256, GEMM_SMEM>>>(
        z,   hrA, Ws1, NRX, 128, 1, gR,
        hsA, hsB, Ws1, bs + DM, NSP, 0, 1);
    k_seg8<<<segBlocks, 256>>>(z, hsA, edge_reaction, edge_species);

    k_pool<<<dim3(2, BGR, 2), 256>>>(hsA, hrA, out);
}